// round 17
// baseline (speedup 1.0000x reference)
#include <cuda_runtime.h>
#include <cstdint>
#include <math.h>

// ============================================================================
// SpikeEncoder final kernel (champion; best measured 209.376 us, rel_err 0.0).
//
// Output [2, B, T, S, F] = 629 MB of {0,1} floats:
//   - rate half:     Bernoulli(sigmoid(x)) vs JAX *partitionable*
//                    threefry2x32(key=(0,42)), per-element counter (0, i),
//                    combine x0^x1 — bit-exact stream (rel_err == 0.0).
//   - temporal half: one-hot at t = int32(sigmoid(x)*10)  (only t<=10 nonzero).
//
// Perf model (validated over 16 rounds): the spike kernel is ISSUE-bound at
// a hard ~0.75 IPC/SMSP on ~67 slots/element (~60 = irreducible ARX core).
// Measured 204 us vs ~200 us modeled floor; HBM 35% (never binding).
// Tested & rejected: IMAD.WIDE/madd pipe rebalance (time-neutral or worse
// under the issue ceiling), manual key-schedule folding (ptxas already does
// it), 8-elem ILP (L0 I$ overflow), 3D grids (-60%), PDL (neutral), block
// size variants (neutral). The only winning lever was deleting issue slots.
// ============================================================================

// Problem dims (fixed by the dataset problem)
#define BB   8
#define TT   100
#define SS   128
#define FF   768
#define SF   (SS * FF)          // 98304
#define BSF  (BB * SF)          // 786432
#define TSF  (TT * SF)          // 9830400
#define NTOT (BB * TSF)         // 78643200  (elements per stacked half)

// Blocks: each covers 2048 consecutive elements of one (b,t) row
// (512 threads x 4 elements).
#define ELEMS_PER_BLK 2048
#define BLKS_PER_ROW  (SF / ELEMS_PER_BLK)   // 48
#define ROWS          (BB * TT)              // 800

// Packed per-(b,s,f) word:
//   bits[9:32) = thresh = ceil(p * 2^23)   (rate:  spike <=> bits32 < thresh<<9)
//   bits[0:9)  = tm = (int)(p * 10.f)      (temporal spike time, 0..10)
// (|tm in the low 9 bits perturbs the rate threshold by <2^-32*512 per draw:
//  expected flips over 78.6M elements ~0.2 — measured rel_err == 0.0.)
__device__ uint32_t g_w32[BSF];

// ---------------------------------------------------------------------------
// Correctly-rounded f32 sigmoid via double-single arithmetic on the fp32 pipe
// (bit-compatible with the f64 reference path per R6-R16: rel_err == 0.0;
// replaced a ~40us FP64 exp() prep with a ~3us fp32-pipe version).
// ---------------------------------------------------------------------------
__device__ __forceinline__ float sigmoid_cr(float x) {
    if (fabsf(x) > 20.0f) {                     // never taken for N(0,1) data
        double pd = 1.0 / (1.0 + exp(-(double)x));
        return (float)pd;
    }
    const float L2E_HI = 1.4426950216293335f;
    const float L2E_LO = 1.9259629911266175e-8f;
    float xn  = -x;
    float thi = xn * L2E_HI;
    float tlo = fmaf(xn, L2E_HI, -thi);
    tlo = fmaf(xn, L2E_LO, tlo);
    float n   = rintf(thi);
    float fhi = thi - n;                        // exact (Cody-Waite)
    const float LN2_HI = 0.6931471824645996f;
    const float LN2_LO = -1.904654323148236e-9f;
    float uhi = fhi * LN2_HI;
    float ulo = fmaf(fhi, LN2_HI, -uhi);
    ulo = fmaf(fhi, LN2_LO, ulo);
    ulo = fmaf(tlo, LN2_HI, ulo);
    float q;
    q = fmaf(2.4801587e-5f, uhi, 1.9841270e-4f);
    q = fmaf(q, uhi, 1.3888889e-3f);
    q = fmaf(q, uhi, 8.3333338e-3f);
    q = fmaf(q, uhi, 4.1666668e-2f);
    q = fmaf(q, uhi, 1.6666667e-1f);
    q = fmaf(q, uhi, 0.5f);
    float u2 = uhi * uhi;
    float v  = u2 * q;
    float c  = fmaf(ulo, uhi, ulo);             // ulo * (1 + uhi)
    float shi = 1.0f + uhi;
    float slo = uhi - (shi - 1.0f);             // Fast2Sum (1 >= |uhi|)
    float ehi = shi + v;
    float elo = (v - (ehi - shi)) + slo + c;    // Fast2Sum (|shi| >= |v|)
    int   ni = (int)n;
    float sc = __int_as_float((ni + 127) << 23);
    ehi *= sc;
    elo *= sc;
    float dhi = 1.0f + ehi;                     // d = 1 + e^{-x} (TwoSum)
    float t1  = dhi - 1.0f;
    float dlo = ((1.0f - (dhi - t1)) + (ehi - t1)) + elo;
    float r   = 1.0f / dhi;                     // ds-refined reciprocal
    float res = fmaf(r, dhi, -1.0f);
    res = fmaf(r, dlo, res);
    return fmaf(-r, res, r);
}

// ---------------------------------------------------------------------------
// Prep: pack threshold<<9 | time per (b,s,f).
// ---------------------------------------------------------------------------
__global__ void __launch_bounds__(256) prep_kernel(const float* __restrict__ feat) {
    int i = blockIdx.x * blockDim.x + threadIdx.x;
    if (i >= BSF) return;
    float p = sigmoid_cr(feat[i]);
    uint32_t thresh = (uint32_t)ceilf(p * 8388608.0f);   // ceil(p * 2^23), exact scale
    uint32_t tm = (uint32_t)(int)(p * 10.0f);            // JAX: int32(p * 10)
    uint32_t w;
    if (thresh >= 0x800000u) w = 0xFFFFFFFFu;            // p==1 edge (never hit)
    else                     w = (thresh << 9) | tm;
    g_w32[i] = w;
}

// ---------------------------------------------------------------------------
// JAX partitionable threefry2x32: per-element 64-bit counter (hi=0, lo=i),
// key = (0, 42), output = x0_final ^ x1_final.  All-SHF, plain-C adds —
// the minimum-slot form; ptxas folds the key injections into IADD3 itself.
// ---------------------------------------------------------------------------
__device__ __forceinline__ uint32_t threefry_bits(uint32_t i) {
    const uint32_t ks0 = 0u;
    const uint32_t ks1 = 42u;
    const uint32_t ks2 = 0x1BD11BDAu ^ 0u ^ 42u;
    uint32_t x0 = 0u + ks0;        // counter hi = 0
    uint32_t x1 = i  + ks1;        // counter lo = element index
#define TF_ROUND(r) { x0 += x1; x1 = __funnelshift_l(x1, x1, (r)); x1 ^= x0; }
    TF_ROUND(13) TF_ROUND(15) TF_ROUND(26) TF_ROUND(6)
    x0 += ks1; x1 += ks2 + 1u;
    TF_ROUND(17) TF_ROUND(29) TF_ROUND(16) TF_ROUND(24)
    x0 += ks2; x1 += ks0 + 2u;
    TF_ROUND(13) TF_ROUND(15) TF_ROUND(26) TF_ROUND(6)
    x0 += ks0; x1 += ks1 + 3u;
    TF_ROUND(17) TF_ROUND(29) TF_ROUND(16) TF_ROUND(24)
    x0 += ks1; x1 += ks2 + 4u;
    TF_ROUND(13) TF_ROUND(15) TF_ROUND(26) TF_ROUND(6)
    x0 += ks2; x1 += ks0 + 5u;
#undef TF_ROUND
    return x0 ^ x1;                // partitionable 32-bit combine
}

// ---------------------------------------------------------------------------
// Fused spike kernel: 4 elems/thread, 512-thread blocks, 1D grid, all index
// math uniform (blockIdx-derived). Rate = single unsigned compare against
// the packed threshold; temporal = one-hot, skipped entirely for the 89% of
// blocks with t > 10. g_w32 (3 MB) stays L2-resident, reused T=100 times.
// ---------------------------------------------------------------------------
__global__ void __launch_bounds__(512) spike_kernel(float* __restrict__ out) {
    const uint32_t blk   = blockIdx.x;                  // 0..38399
    const uint32_t row   = blk / BLKS_PER_ROW;          // (b*TT + t), uniform
    const uint32_t chunk = blk - row * BLKS_PER_ROW;    // 0..47, uniform
    const uint32_t b     = row / TT;                    // uniform
    const uint32_t t     = row - b * TT;                // uniform

    const uint32_t lane4 = threadIdx.x * 4u;
    const uint32_t sf    = chunk * (uint32_t)ELEMS_PER_BLK + lane4;
    const uint32_t j0    = blk * (uint32_t)ELEMS_PER_BLK + lane4;

    const uint4 wv = *reinterpret_cast<const uint4*>(&g_w32[b * SF + sf]);
    const uint32_t w[4] = {wv.x, wv.y, wv.z, wv.w};

    uint32_t bits[4];
#pragma unroll
    for (int k = 0; k < 4; ++k)
        bits[k] = threefry_bits(j0 + (uint32_t)k);

    float rate[4];
#pragma unroll
    for (int k = 0; k < 4; ++k)
        rate[k] = (bits[k] < w[k]) ? 1.0f : 0.0f;

    *reinterpret_cast<float4*>(out + j0) =
        make_float4(rate[0], rate[1], rate[2], rate[3]);

    float4 tv;
    if (t <= 10u) {                            // block-uniform branch
        tv.x = ((w[0] & 511u) == t) ? 1.0f : 0.0f;
        tv.y = ((w[1] & 511u) == t) ? 1.0f : 0.0f;
        tv.z = ((w[2] & 511u) == t) ? 1.0f : 0.0f;
        tv.w = ((w[3] & 511u) == t) ? 1.0f : 0.0f;
    } else {
        tv = make_float4(0.0f, 0.0f, 0.0f, 0.0f);
    }
    *reinterpret_cast<float4*>(out + (uint32_t)NTOT + j0) = tv;
}

extern "C" void kernel_launch(void* const* d_in, const int* in_sizes, int n_in,
                              void* d_out, int out_size) {
    const float* features = (const float*)d_in[0];
    float* out = (float*)d_out;

    // 786432 / 256 = 3072 blocks (exact)
    prep_kernel<<<BSF / 256, 256>>>(features);

    // 38,400 blocks x 512 threads x 4 elems = NTOT (exact), 1D grid
    spike_kernel<<<ROWS * BLKS_PER_ROW, 512>>>(out);
}